// round 8
// baseline (speedup 1.0000x reference)
#include <cuda_runtime.h>
#include <cuda_fp16.h>
#include <cstdint>
#include <cstddef>

// ---------------------------------------------------------------------------
// TokenPacker round 8: 2-term fp16 split GEMM, ONE 512-thread CTA (128x256
// tile, 16 warps 4Mx4N), BK=64, 3-stage cp.async.cg pipeline, load-ahead-2,
// single __syncthreads per k-tile. STS -33%, barriers/iter -50%.
// ---------------------------------------------------------------------------

#define E_DIM 1024
#define NQ 144
#define TN 576
#define NB 64
#define M_BIG  (NB * TN)   // 36864
#define M_SML  (NB * NQ)   // 9216

#define WSLOT ((size_t)E_DIM * E_DIM)

// fp16 hi/lo activation planes
__device__ __half g_xf_h [(size_t)M_BIG * E_DIM];
__device__ __half g_xf_l [(size_t)M_BIG * E_DIM];
__device__ __half g_x_h  [(size_t)M_SML * E_DIM];
__device__ __half g_x_l  [(size_t)M_SML * E_DIM];
__device__ __half g_tmp_h[(size_t)M_BIG * E_DIM];
__device__ __half g_tmp_l[(size_t)M_BIG * E_DIM];
__device__ __half g_kn_h [(size_t)M_BIG * E_DIM];
__device__ __half g_kn_l [(size_t)M_BIG * E_DIM];
__device__ __half g_vn_h [(size_t)M_BIG * E_DIM];
__device__ __half g_vn_l [(size_t)M_BIG * E_DIM];
__device__ __half g_qn_h [(size_t)M_SML * E_DIM];
__device__ __half g_qn_l [(size_t)M_SML * E_DIM];
__device__ __half g_at_h [(size_t)M_SML * E_DIM];
__device__ __half g_at_l [(size_t)M_SML * E_DIM];
// fp16 weight slots (hi only): 0=wq 1=wk1 2=wk2 3=wv1 4=wv2 5,6,7=in_w 8=out_w
__device__ __half g_w_h[9 * WSLOT];
// fp32 scratch
__device__ float g_key[(size_t)M_BIG * E_DIM];
__device__ float g_val[(size_t)M_BIG * E_DIM];
__device__ float g_qry[(size_t)M_SML * E_DIM];
__device__ float g_qh [(size_t)M_SML * E_DIM];
__device__ float g_kh [(size_t)M_BIG * E_DIM];
__device__ float g_vh [(size_t)M_BIG * E_DIM];

// ---------------------------------------------------------------------------
// helpers
// ---------------------------------------------------------------------------
__device__ __forceinline__ void mma16(float* c, const uint32_t* a, const uint32_t* b) {
    asm("mma.sync.aligned.m16n8k16.row.col.f32.f16.f16.f32 "
        "{%0,%1,%2,%3}, {%4,%5,%6,%7}, {%8,%9}, {%0,%1,%2,%3};\n"
        : "+f"(c[0]), "+f"(c[1]), "+f"(c[2]), "+f"(c[3])
        : "r"(a[0]), "r"(a[1]), "r"(a[2]), "r"(a[3]), "r"(b[0]), "r"(b[1]));
}

__device__ __forceinline__ void ldsm_x4(uint32_t* r, uint32_t addr) {
    asm volatile("ldmatrix.sync.aligned.m8n8.x4.shared.b16 {%0,%1,%2,%3}, [%4];"
        : "=r"(r[0]), "=r"(r[1]), "=r"(r[2]), "=r"(r[3]) : "r"(addr));
}

__device__ __forceinline__ void cp_async16(uint32_t saddr, const void* gmem) {
    asm volatile("cp.async.cg.shared.global [%0], [%1], 16;\n" :: "r"(saddr), "l"(gmem));
}
__device__ __forceinline__ void cp_commit() { asm volatile("cp.async.commit_group;\n"); }
template <int N>
__device__ __forceinline__ void cp_wait() { asm volatile("cp.async.wait_group %0;\n" :: "n"(N)); }

__device__ __forceinline__ void split_store2(__half* __restrict__ hi, __half* __restrict__ lo,
                                             size_t off, float a, float b) {
    __half h0 = __float2half_rn(a), h1 = __float2half_rn(b);
    __half l0 = __float2half_rn(a - __half2float(h0));
    __half l1 = __float2half_rn(b - __half2float(h1));
    *(__half2*)(hi + off) = __halves2half2(h0, h1);
    *(__half2*)(lo + off) = __halves2half2(l0, l1);
}

__device__ __forceinline__ float gelu_exact(float x) {
    return 0.5f * x * (1.0f + erff(x * 0.7071067811865476f));
}

// ---------------------------------------------------------------------------
// split kernels
// ---------------------------------------------------------------------------
__global__ __launch_bounds__(256)
void split_f32(const float4* __restrict__ src, __half* __restrict__ hi,
               __half* __restrict__ lo, int n4)
{
    int i = blockIdx.x * blockDim.x + threadIdx.x;
    if (i < n4) {
        float4 v = src[i];
        size_t off = (size_t)i * 4;
        split_store2(hi, lo, off,     v.x, v.y);
        split_store2(hi, lo, off + 2, v.z, v.w);
    }
}

struct WPtrs { const float4* s[9]; };

__global__ __launch_bounds__(256)
void cvt_weights(WPtrs p, __half* __restrict__ w_h)
{
    const int slot = blockIdx.y;
    const float4* src = p.s[slot];
    __half* dst = w_h + (size_t)slot * WSLOT;
    int i = blockIdx.x * blockDim.x + threadIdx.x;
    float4 v = src[i];
    __half2 a = __halves2half2(__float2half_rn(v.x), __float2half_rn(v.y));
    __half2 b = __halves2half2(__float2half_rn(v.z), __float2half_rn(v.w));
    *(__half2*)(dst + (size_t)i * 4)     = a;
    *(__half2*)(dst + (size_t)i * 4 + 2) = b;
}

// ---------------------------------------------------------------------------
// GEMM: C[M,1024] = (Ah+Al)[M,1024] @ Bh^T, 2 mma terms, ldmatrix.
// CTA tile 128x256, 512 threads (16 warps, 4Mx4N), warp tile 32x64.
// BK=64, 3 stages, load-ahead-2, ONE __syncthreads per k-tile.
// MODE 0: fp32 out. MODE 1: fp32 + bias. MODE 2: gelu(+bias) -> hi/lo planes.
// ---------------------------------------------------------------------------
#define BK 64
#define BN 256
#define SROW 144                       // bytes per smem row (64+8 halves)
#define A_PLANE_B (128 * SROW)         // 18432 bytes (per A plane)
#define B_PLANE_B (256 * SROW)         // 36864 bytes
#define STAGE_B (2 * A_PLANE_B + B_PLANE_B)   // 73728 bytes
#define NSTAGE 3
#define GEMM_SMEM (NSTAGE * STAGE_B)   // 221184 bytes
#define NKT (E_DIM / BK)               // 16

template<int MODE>
__global__ __launch_bounds__(512, 1)
void gemm_f16x2(const __half* __restrict__ Ah, const __half* __restrict__ Al,
                const __half* __restrict__ Bh,
                const float* __restrict__ bias,
                float* __restrict__ Cf,
                __half* __restrict__ Chi, __half* __restrict__ Clo)
{
    extern __shared__ __align__(128) char smraw[];
    const uint32_t smem_base = (uint32_t)__cvta_generic_to_shared(smraw);
    const int tid  = threadIdx.x;
    const int lane = tid & 31;
    const int wid  = tid >> 5;
    const int wm   = (wid >> 2) * 32;   // warp M offset (0,32,64,96)
    const int wn   = (wid & 3) * 64;    // warp N offset (0,64,128,192)
    const int bm   = blockIdx.y;
    const int bn   = blockIdx.x;

    float acc[2][8][4];
    #pragma unroll
    for (int mt = 0; mt < 2; mt++)
        #pragma unroll
        for (int nt = 0; nt < 8; nt++)
            #pragma unroll
            for (int i = 0; i < 4; i++) acc[mt][nt][i] = 0.0f;

    // ldmatrix per-lane byte offsets (plane-relative), loop-invariant
    uint32_t aoff[2], boff[4];
    #pragma unroll
    for (int mt = 0; mt < 2; mt++)
        aoff[mt] = (wm + mt * 16 + (lane & 15)) * SROW + ((lane >> 4) << 4);
    #pragma unroll
    for (int j = 0; j < 4; j++)
        boff[j] = (wn + (2 * j + ((lane >> 4) & 1)) * 8 + (lane & 7)) * SROW
                  + (((lane >> 3) & 1) << 4);

    // tile loader: A 2 planes x 128 rows x 8 chunks + B 256 rows x 8 chunks
    // = 4096 chunks(16B) / 512 threads = 8 per thread
    auto load_tiles = [&](int kt, int stg) {
        const int k0 = kt * BK;
        const uint32_t base = smem_base + stg * STAGE_B;
        #pragma unroll
        for (int t = 0; t < 4; t++) {            // A planes: 2048 chunks
            int idx = tid + t * 512;
            int plane = idx >> 10;
            int rem = idx & 1023;
            int row = rem >> 3, c = rem & 7;
            const __half* src = (plane ? Al : Ah)
                              + (size_t)(bm * 128 + row) * E_DIM + k0 + c * 8;
            cp_async16(base + plane * A_PLANE_B + row * SROW + c * 16, src);
        }
        #pragma unroll
        for (int t = 0; t < 4; t++) {            // B plane: 2048 chunks
            int idx = tid + t * 512;
            int row = idx >> 3, c = idx & 7;
            const __half* src = Bh + (size_t)(bn * BN + row) * E_DIM + k0 + c * 8;
            cp_async16(base + 2 * A_PLANE_B + row * SROW + c * 16, src);
        }
    };

    load_tiles(0, 0); cp_commit();
    load_tiles(1, 1); cp_commit();

    int stg = 0;            // stage of tile kt
    int stg2 = 2;           // stage for tile kt+2
    for (int kt = 0; kt < NKT; kt++) {
        cp_wait<1>();        // group kt done (groups complete in commit order)
        __syncthreads();     // all warps finished compute kt-1 -> stage stg2 free

        if (kt + 2 < NKT) load_tiles(kt + 2, stg2);
        cp_commit();         // empty group near the end keeps counts aligned

        const uint32_t sA  = smem_base + stg * STAGE_B;
        const uint32_t sAl = sA + A_PLANE_B;
        const uint32_t sB  = sA + 2 * A_PLANE_B;

        #pragma unroll
        for (int ks = 0; ks < 4; ks++) {
            const uint32_t kbb = ks * 32;        // 16 halves = 32 bytes per half-step
            uint32_t ah0[4], ah1[4], al0[4], al1[4];
            ldsm_x4(ah0, sA  + aoff[0] + kbb);
            ldsm_x4(ah1, sA  + aoff[1] + kbb);
            ldsm_x4(al0, sAl + aoff[0] + kbb);
            ldsm_x4(al1, sAl + aoff[1] + kbb);
            uint32_t bb[4][4];
            #pragma unroll
            for (int j = 0; j < 4; j++)
                ldsm_x4(bb[j], sB + boff[j] + kbb);

            #pragma unroll
            for (int nt = 0; nt < 8; nt++)
                mma16(acc[0][nt], ah0, &bb[nt >> 1][(nt & 1) * 2]);
            #pragma unroll
            for (int nt = 0; nt < 8; nt++)
                mma16(acc[1][nt], ah1, &bb[nt >> 1][(nt & 1) * 2]);
            #pragma unroll
            for (int nt = 0; nt < 8; nt++)
                mma16(acc[0][nt], al0, &bb[nt >> 1][(nt & 1) * 2]);
            #pragma unroll
            for (int nt = 0; nt < 8; nt++)
                mma16(acc[1][nt], al1, &bb[nt >> 1][(nt & 1) * 2]);
        }
        stg = (stg == 2) ? 0 : stg + 1;
        stg2 = (stg2 == 2) ? 0 : stg2 + 1;
    }

    // epilogue
    #pragma unroll
    for (int mt = 0; mt < 2; mt++) {
        #pragma unroll
        for (int nt = 0; nt < 8; nt++) {
            int row0 = bm * 128 + wm + mt * 16 + (lane >> 2);
            int col  = bn * BN + wn + nt * 8 + ((lane & 3) << 1);
            float bv0 = 0.0f, bv1 = 0.0f;
            if (MODE != 0) { bv0 = bias[col]; bv1 = bias[col + 1]; }
            float c0 = acc[mt][nt][0] + bv0;
            float c1 = acc[mt][nt][1] + bv1;
            float c2 = acc[mt][nt][2] + bv0;
            float c3 = acc[mt][nt][3] + bv1;
            if (MODE == 2) {
                c0 = gelu_exact(c0); c1 = gelu_exact(c1);
                c2 = gelu_exact(c2); c3 = gelu_exact(c3);
                size_t o0 = (size_t)row0 * E_DIM + col;
                size_t o1 = (size_t)(row0 + 8) * E_DIM + col;
                split_store2(Chi, Clo, o0, c0, c1);
                split_store2(Chi, Clo, o1, c2, c3);
            } else {
                *(float2*)(Cf + (size_t)row0 * E_DIM + col)       = make_float2(c0, c1);
                *(float2*)(Cf + (size_t)(row0 + 8) * E_DIM + col) = make_float2(c2, c3);
            }
        }
    }
}

// ---------------------------------------------------------------------------
// LayerNorm over last dim (1024) -> fp16 hi/lo planes. 256 thr per row.
// ---------------------------------------------------------------------------
__global__ __launch_bounds__(256)
void ln_split(const float* __restrict__ X, __half* __restrict__ Hi, __half* __restrict__ Lo,
              const float* __restrict__ w, const float* __restrict__ b)
{
    const size_t row = blockIdx.x;
    const float4* xp = (const float4*)(X + row * E_DIM);
    const int tid  = threadIdx.x;
    const int lane = tid & 31;
    const int wid  = tid >> 5;

    float4 v = xp[tid];
    float s  = v.x + v.y + v.z + v.w;
    float ss = v.x * v.x + v.y * v.y + v.z * v.z + v.w * v.w;
    #pragma unroll
    for (int off = 16; off; off >>= 1) {
        s  += __shfl_xor_sync(0xffffffffu, s, off);
        ss += __shfl_xor_sync(0xffffffffu, ss, off);
    }
    __shared__ float rs[8], rss[8];
    if (lane == 0) { rs[wid] = s; rss[wid] = ss; }
    __syncthreads();
    float ts = 0.0f, tss = 0.0f;
    #pragma unroll
    for (int i = 0; i < 8; i++) { ts += rs[i]; tss += rss[i]; }
    const float mean = ts * (1.0f / 1024.0f);
    const float var  = tss * (1.0f / 1024.0f) - mean * mean;
    const float inv  = rsqrtf(var + 1e-6f);

    const float4 w4 = ((const float4*)w)[tid];
    const float4 b4 = ((const float4*)b)[tid];
    float y0 = (v.x - mean) * inv * w4.x + b4.x;
    float y1 = (v.y - mean) * inv * w4.y + b4.y;
    float y2 = (v.z - mean) * inv * w4.z + b4.z;
    float y3 = (v.w - mean) * inv * w4.w + b4.w;
    size_t off = row * E_DIM + (size_t)tid * 4;
    split_store2(Hi, Lo, off,     y0, y1);
    split_store2(Hi, Lo, off + 2, y2, y3);
}

// ---------------------------------------------------------------------------
// Attention: per (n, q): 8 heads x (1 query, 4 keys); output -> hi/lo planes.
// ---------------------------------------------------------------------------
__global__ __launch_bounds__(256)
void attn_split(const float* __restrict__ qh, const float* __restrict__ kh,
                const float* __restrict__ vh, __half* __restrict__ Ohi,
                __half* __restrict__ Olo)
{
    const int bq   = blockIdx.x;
    const int n    = bq / NQ;
    const int q    = bq - n * NQ;
    const int h    = threadIdx.x >> 5;
    const int lane = threadIdx.x & 31;
    const int qr   = q / 12;
    const int qc   = q - qr * 12;

    const size_t qoff = (size_t)bq * E_DIM + h * 128 + lane * 4;
    const float4 qv = *(const float4*)(qh + qoff);

    float s[4];
    float4 vv[4];
    #pragma unroll
    for (int kk = 0; kk < 4; kk++) {
        const int t = (qr * 2 + (kk >> 1)) * 24 + qc * 2 + (kk & 1);
        const size_t krow = (size_t)(n * TN + t) * E_DIM + h * 128 + lane * 4;
        const float4 k4 = *(const float4*)(kh + krow);
        vv[kk] = *(const float4*)(vh + krow);
        float d = qv.x * k4.x + qv.y * k4.y + qv.z * k4.z + qv.w * k4.w;
        #pragma unroll
        for (int off = 16; off; off >>= 1) d += __shfl_xor_sync(0xffffffffu, d, off);
        s[kk] = d * 0.08838834764831845f;
    }
    const float m = fmaxf(fmaxf(s[0], s[1]), fmaxf(s[2], s[3]));
    float p[4], sum = 0.0f;
    #pragma unroll
    for (int kk = 0; kk < 4; kk++) { p[kk] = expf(s[kk] - m); sum += p[kk]; }
    const float inv = 1.0f / sum;
    float4 o = make_float4(0.f, 0.f, 0.f, 0.f);
    #pragma unroll
    for (int kk = 0; kk < 4; kk++) {
        const float pk = p[kk] * inv;
        o.x += pk * vv[kk].x; o.y += pk * vv[kk].y;
        o.z += pk * vv[kk].z; o.w += pk * vv[kk].w;
    }
    split_store2(Ohi, Olo, qoff,     o.x, o.y);
    split_store2(Ohi, Olo, qoff + 2, o.z, o.w);
}

// ---------------------------------------------------------------------------
// launch
// ---------------------------------------------------------------------------
extern "C" void kernel_launch(void* const* d_in, const int* in_sizes, int n_in,
                              void* d_out, int out_size)
{
    const float* x      = (const float*)d_in[0];
    const float* x_feat = (const float*)d_in[1];
    const float* w_q    = (const float*)d_in[2];
    const float* w_k1   = (const float*)d_in[3];
    const float* b_k1   = (const float*)d_in[4];
    const float* w_k2   = (const float*)d_in[5];
    const float* b_k2   = (const float*)d_in[6];
    const float* w_v1   = (const float*)d_in[7];
    const float* b_v1   = (const float*)d_in[8];
    const float* w_v2   = (const float*)d_in[9];
    const float* b_v2   = (const float*)d_in[10];
    const float* ln_q_w = (const float*)d_in[11];
    const float* ln_q_b = (const float*)d_in[12];
    const float* ln_k_w = (const float*)d_in[13];
    const float* ln_k_b = (const float*)d_in[14];
    const float* ln_v_w = (const float*)d_in[15];
    const float* ln_v_b = (const float*)d_in[16];
    const float* in_w   = (const float*)d_in[17];
    const float* in_b   = (const float*)d_in[18];
    const float* out_w  = (const float*)d_in[19];
    const float* out_b  = (const float*)d_in[20];
    float* out = (float*)d_out;

    __half *xf_h, *xf_l, *x_h, *x_l, *tmp_h, *tmp_l, *kn_h, *kn_l, *vn_h, *vn_l;
    __half *qn_h, *qn_l, *at_h, *at_l, *w_h;
    float *key, *val, *qry, *qh, *kh, *vh;
    cudaGetSymbolAddress((void**)&xf_h, g_xf_h);  cudaGetSymbolAddress((void**)&xf_l, g_xf_l);
    cudaGetSymbolAddress((void**)&x_h,  g_x_h);   cudaGetSymbolAddress((void**)&x_l,  g_x_l);
    cudaGetSymbolAddress((void**)&tmp_h,g_tmp_h); cudaGetSymbolAddress((void**)&tmp_l,g_tmp_l);
    cudaGetSymbolAddress((void**)&kn_h, g_kn_h);  cudaGetSymbolAddress((void**)&kn_l, g_kn_l);
    cudaGetSymbolAddress((void**)&vn_h, g_vn_h);  cudaGetSymbolAddress((void**)&vn_l, g_vn_l);
    cudaGetSymbolAddress((void**)&qn_h, g_qn_h);  cudaGetSymbolAddress((void**)&qn_l, g_qn_l);
    cudaGetSymbolAddress((void**)&at_h, g_at_h);  cudaGetSymbolAddress((void**)&at_l, g_at_l);
    cudaGetSymbolAddress((void**)&w_h,  g_w_h);
    cudaGetSymbolAddress((void**)&key,  g_key);   cudaGetSymbolAddress((void**)&val,  g_val);
    cudaGetSymbolAddress((void**)&qry,  g_qry);   cudaGetSymbolAddress((void**)&qh,   g_qh);
    cudaGetSymbolAddress((void**)&kh,   g_kh);    cudaGetSymbolAddress((void**)&vh,   g_vh);

    cudaFuncSetAttribute(gemm_f16x2<0>, cudaFuncAttributeMaxDynamicSharedMemorySize, GEMM_SMEM);
    cudaFuncSetAttribute(gemm_f16x2<1>, cudaFuncAttributeMaxDynamicSharedMemorySize, GEMM_SMEM);
    cudaFuncSetAttribute(gemm_f16x2<2>, cudaFuncAttributeMaxDynamicSharedMemorySize, GEMM_SMEM);

    dim3 blk(256);
    dim3 gblk(512);
    dim3 gridBig(E_DIM / BN, M_BIG / 128);   // (4, 288)
    dim3 gridSml(E_DIM / BN, M_SML / 128);   // (4, 72)

    // split inputs (hi+lo — A operands)
    {
        int n4 = (int)((size_t)M_BIG * E_DIM / 4);
        split_f32<<<(n4 + 255) / 256, blk>>>((const float4*)x_feat, xf_h, xf_l, n4);
    }
    {
        int n4 = (int)((size_t)M_SML * E_DIM / 4);
        split_f32<<<(n4 + 255) / 256, blk>>>((const float4*)x, x_h, x_l, n4);
    }
    // convert all 9 weight slots in one launch (hi only — B operands)
    {
        WPtrs p;
        p.s[0] = (const float4*)w_q;
        p.s[1] = (const float4*)w_k1;
        p.s[2] = (const float4*)w_k2;
        p.s[3] = (const float4*)w_v1;
        p.s[4] = (const float4*)w_v2;
        p.s[5] = (const float4*)in_w;
        p.s[6] = (const float4*)(in_w + WSLOT);
        p.s[7] = (const float4*)(in_w + 2 * WSLOT);
        p.s[8] = (const float4*)out_w;
        dim3 g((int)(WSLOT / 4 / 256), 9);
        cvt_weights<<<g, blk>>>(p, w_h);
    }

    // key path
    gemm_f16x2<2><<<gridBig, gblk, GEMM_SMEM>>>(xf_h, xf_l, w_h + 1 * WSLOT,
                                                b_k1, nullptr, tmp_h, tmp_l);
    gemm_f16x2<1><<<gridBig, gblk, GEMM_SMEM>>>(tmp_h, tmp_l, w_h + 2 * WSLOT,
                                                b_k2, key, nullptr, nullptr);
    ln_split<<<M_BIG, blk>>>(key, kn_h, kn_l, ln_k_w, ln_k_b);
    // value path
    gemm_f16x2<2><<<gridBig, gblk, GEMM_SMEM>>>(xf_h, xf_l, w_h + 3 * WSLOT,
                                                b_v1, nullptr, tmp_h, tmp_l);
    gemm_f16x2<1><<<gridBig, gblk, GEMM_SMEM>>>(tmp_h, tmp_l, w_h + 4 * WSLOT,
                                                b_v2, val, nullptr, nullptr);
    ln_split<<<M_BIG, blk>>>(val, vn_h, vn_l, ln_v_w, ln_v_b);
    // query path
    gemm_f16x2<0><<<gridSml, gblk, GEMM_SMEM>>>(x_h, x_l, w_h + 0 * WSLOT,
                                                nullptr, qry, nullptr, nullptr);
    ln_split<<<M_SML, blk>>>(qry, qn_h, qn_l, ln_q_w, ln_q_b);
    // in-proj q/k/v
    gemm_f16x2<1><<<gridSml, gblk, GEMM_SMEM>>>(qn_h, qn_l, w_h + 5 * WSLOT,
                                                in_b, qh, nullptr, nullptr);
    gemm_f16x2<1><<<gridBig, gblk, GEMM_SMEM>>>(kn_h, kn_l, w_h + 6 * WSLOT,
                                                in_b + E_DIM, kh, nullptr, nullptr);
    gemm_f16x2<1><<<gridBig, gblk, GEMM_SMEM>>>(vn_h, vn_l, w_h + 7 * WSLOT,
                                                in_b + 2 * E_DIM, vh, nullptr, nullptr);
    // attention
    attn_split<<<M_SML, blk>>>(qh, kh, vh, at_h, at_l);
    // out-proj -> d_out
    gemm_f16x2<1><<<gridSml, gblk, GEMM_SMEM>>>(at_h, at_l, w_h + 8 * WSLOT,
                                                out_b, out, nullptr, nullptr);
}